// round 15
// baseline (speedup 1.0000x reference)
#include <cuda_runtime.h>
#include <cuda_fp16.h>
#include <cstdint>

// GaussianKDE via legacy mma.sync fp16 m16n8k16 (fp32 accum) + fused exp epilogue.
// R14 base (135.6us) + 2 CTAs/SM: tile split into two sequential 64-col halves
// (32-reg accumulator) so regs fit 128 under __launch_bounds__(256,2).
// Grid 288 = one wave at occ 2; HW arbiter overlaps one CTA's epilogue with
// the other's MMA burst.
// out[q] = (norm/N) * a[q] * sum_n b[n] * exp2((log2e*f_q) . x_n)

#define DCONST 64
#define QCAP   4096
#define NCAP   50048        // 391 * 128
#define QTILE  128
#define NTILE  128
#define NCHUNK 9            // 32 q-tiles * 9 = 288 blocks = 1 wave @ occ 2
#define XS2    36           // uint32 (fp16x2) row stride: 32 pairs + 4 pad
#define LOG2E  1.44269504088896340736f

#define OFF_F  0
#define TILE_B (128 * XS2 * 4)          // 18432 bytes per 128-row fp16 tile
#define OFF_X  (OFF_F + TILE_B)         // 2 buffers
#define OFF_BS (OFF_X + 2 * TILE_B)     // bs[2][128] floats
#define OFF_RED (OFF_BS + 1024)         // red[256] floats
#define SMEM_TOTAL (OFF_RED + 1024)     // ~57 KB -> 2 CTAs fit in 228 KB

__device__ uint32_t g_fh[QCAP * 32];    // fp16x2(log2e * f)
__device__ float    g_a[QCAP];
__device__ uint32_t g_xh[NCAP * 32];    // fp16x2(x)
__device__ float    g_b[NCAP];

// ---------------------------------------------------------------------------
__device__ __forceinline__ uint32_t smem_u32(const void* p) {
    uint32_t a;
    asm("{ .reg .u64 t; cvta.to.shared.u64 t, %1; cvt.u32.u64 %0, t; }"
        : "=r"(a) : "l"(p));
    return a;
}
__device__ __forceinline__ void cp16(uint32_t dst, const void* src) {
    asm volatile("cp.async.cg.shared.global [%0], [%1], 16;"
                 :: "r"(dst), "l"(src) : "memory");
}
__device__ __forceinline__ void mma16(float* d, const uint32_t* a,
                                      uint32_t b0, uint32_t b1) {
    asm volatile("mma.sync.aligned.m16n8k16.row.col.f32.f16.f16.f32 "
                 "{%0,%1,%2,%3}, {%4,%5,%6,%7}, {%8,%9}, {%0,%1,%2,%3};"
                 : "+f"(d[0]), "+f"(d[1]), "+f"(d[2]), "+f"(d[3])
                 : "r"(a[0]), "r"(a[1]), "r"(a[2]), "r"(a[3]),
                   "r"(b0), "r"(b1));
}
__device__ __forceinline__ uint32_t pack_h2(float lo, float hi) {
    __half2 h = __floats2half2_rn(lo, hi);
    return *(uint32_t*)&h;
}
__device__ __forceinline__ float ex2(float x) {
    float r;
    asm("ex2.approx.f32 %0, %1;" : "=f"(r) : "f"(x));
    return r;
}

// ---------------------------------------------------------------------------
// Fused prep: blocks [0, FB) do the F side, blocks [FB, ...) the X side.
__global__ void prep_kernel(const float* __restrict__ feat,
                            const float* __restrict__ bw,
                            const float* __restrict__ ds,
                            float* __restrict__ out, int Q, int N, int FB) {
    int tid = threadIdx.x;
    if ((int)blockIdx.x < FB) {
        __shared__ float bws[DCONST][DCONST];
        for (int i = tid; i < DCONST * DCONST; i += 256)
            bws[i / DCONST][i % DCONST] = bw[i];
        __syncthreads();
        int q = blockIdx.x * 256 + tid;
        if (q >= Q) return;

        float r[DCONST];
        const float4* fr = (const float4*)(feat + (size_t)q * DCONST);
#pragma unroll
        for (int v = 0; v < DCONST / 4; v++) {
            float4 t = fr[v];
            r[4 * v + 0] = t.x; r[4 * v + 1] = t.y;
            r[4 * v + 2] = t.z; r[4 * v + 3] = t.w;
        }
        float fv[DCONST];
        float f2 = 0.0f;
#pragma unroll 4
        for (int d = 0; d < DCONST; d++) {
            float acc = 0.0f;
#pragma unroll
            for (int k = 0; k < DCONST; k++) acc = fmaf(r[k], bws[k][d], acc);
            fv[d] = acc * LOG2E;
            f2 = fmaf(acc, acc, f2);
        }
#pragma unroll
        for (int p = 0; p < 32; p++)
            g_fh[(size_t)q * 32 + p] = pack_h2(fv[2 * p], fv[2 * p + 1]);
        g_a[q] = expf(-0.5f * f2);
        out[q] = 0.0f;
    } else {
        int n = (blockIdx.x - FB) * 256 + tid;
        if (n >= NCAP) return;
        if (n < N) {
            float x2 = 0.0f;
            const float4* r4 = (const float4*)(ds + (size_t)n * DCONST);
#pragma unroll
            for (int v = 0; v < DCONST / 4; v++) {
                float4 t = r4[v];
                g_xh[(size_t)n * 32 + 2 * v + 0] = pack_h2(t.x, t.y);
                g_xh[(size_t)n * 32 + 2 * v + 1] = pack_h2(t.z, t.w);
                x2 = fmaf(t.x, t.x, x2); x2 = fmaf(t.y, t.y, x2);
                x2 = fmaf(t.z, t.z, x2); x2 = fmaf(t.w, t.w, x2);
            }
            g_b[n] = expf(-0.5f * x2);
        } else {
            uint4 z = make_uint4(0, 0, 0, 0);
#pragma unroll
            for (int i = 0; i < 8; i++)
                *(uint4*)(g_xh + (size_t)n * 32 + 4 * i) = z;
            g_b[n] = 0.0f;
        }
    }
}

// ---------------------------------------------------------------------------
// Main kernel: 128(Q) x 128(N) tile per block, 256 threads (8 warps), 2 CTAs/SM.
// Warp = 32(Q) x 64(N), processed as two sequential 32-col halves so the
// accumulator is 32 regs (fits 128-reg budget for occupancy 2).
__global__ __launch_bounds__(256, 2) void kde_mma_kernel(
    const float* __restrict__ norm, float* __restrict__ out,
    int Q, int N, int NT) {
    extern __shared__ char smem[];
    const uint32_t sb = smem_u32(smem);
    const uint32_t* fhu = (const uint32_t*)(smem + OFF_F);
    const int tid = threadIdx.x, lane = tid & 31, wid = tid >> 5;
    const int wq = wid >> 1, wn = wid & 1;
    const int q0 = blockIdx.x * QTILE;
    const int t0 = (blockIdx.y * NT) / NCHUNK;
    const int t1 = ((blockIdx.y + 1) * NT) / NCHUNK;
    const int cnt = t1 - t0;

    // Stage F tile and first X tile via cp.async (one group).
#pragma unroll
    for (int i = 0; i < 4; i++) {
        int e = tid + (i << 8);
        int row = e >> 3, c = e & 7;
        cp16(sb + OFF_F + row * (XS2 * 4) + c * 16,
             g_fh + (size_t)(q0 + row) * 32 + c * 4);
    }
    {
        int n0 = t0 * NTILE;
#pragma unroll
        for (int i = 0; i < 4; i++) {
            int e = tid + (i << 8);
            int row = e >> 3, c = e & 7;
            cp16(sb + OFF_X + row * (XS2 * 4) + c * 16,
                 g_xh + (size_t)(n0 + row) * 32 + c * 4);
        }
        if (tid < 32) cp16(sb + OFF_BS + tid * 16, g_b + n0 + tid * 4);
    }
    asm volatile("cp.async.commit_group;");

    const int rA = wq * 32 + (lane >> 2);
    const int cA = lane & 3;
    const int colB = lane >> 2;

    uint32_t ah[2][4][4];     // A fragments, 4 k-steps, register-resident
    bool a_loaded = false;
    float racc[2][2] = {{0.f, 0.f}, {0.f, 0.f}};

    for (int j = 0; j < cnt; j++) {
        const int b = j & 1;
        if (j + 1 < cnt) {
            // Prefetch next X tile into the other buffer.
            int n0 = (t0 + j + 1) * NTILE;
            int bb = (j + 1) & 1;
#pragma unroll
            for (int i = 0; i < 4; i++) {
                int e = tid + (i << 8);
                int row = e >> 3, c = e & 7;
                cp16(sb + OFF_X + bb * TILE_B + row * (XS2 * 4) + c * 16,
                     g_xh + (size_t)(n0 + row) * 32 + c * 4);
            }
            if (tid < 32) cp16(sb + OFF_BS + bb * 512 + tid * 16, g_b + n0 + tid * 4);
            asm volatile("cp.async.commit_group;");
            asm volatile("cp.async.wait_group 1;");
        } else {
            asm volatile("cp.async.wait_group 0;");
        }
        __syncthreads();

        if (!a_loaded) {    // F tile resident after first wait
            a_loaded = true;
#pragma unroll
            for (int qs = 0; qs < 2; qs++)
#pragma unroll
                for (int kk = 0; kk < 4; kk++) {
                    const uint32_t* p = fhu + (rA + qs * 16) * XS2 + kk * 8 + cA;
                    ah[qs][kk][0] = p[0];
                    ah[qs][kk][1] = p[8 * XS2];
                    ah[qs][kk][2] = p[4];
                    ah[qs][kk][3] = p[8 * XS2 + 4];
                }
        }

        const uint32_t* xp = (const uint32_t*)(smem + OFF_X + b * TILE_B);

        // Two sequential 32-col halves: 32-reg accumulator each.
#pragma unroll
        for (int h = 0; h < 2; h++) {
            const int nbase = wn * 64 + h * 32;
            float acc[2][4][4];
#pragma unroll
            for (int qs = 0; qs < 2; qs++)
#pragma unroll
                for (int ns = 0; ns < 4; ns++)
#pragma unroll
                    for (int i = 0; i < 4; i++) acc[qs][ns][i] = 0.f;

#pragma unroll
            for (int kk = 0; kk < 4; kk++) {
#pragma unroll
                for (int ns = 0; ns < 4; ns++) {
                    const uint32_t* pb = xp + (nbase + ns * 8 + colB) * XS2 + kk * 8;
                    uint32_t b0 = pb[cA];
                    uint32_t b1 = pb[cA + 4];
                    mma16(acc[0][ns], ah[0][kk], b0, b1);
                    mma16(acc[1][ns], ah[1][kk], b0, b1);
                }
            }

            const float* bsp = (const float*)(smem + OFF_BS + b * 512)
                               + nbase + 2 * (lane & 3);
#pragma unroll
            for (int ns = 0; ns < 4; ns++) {
                float2 bv = *(const float2*)(bsp + ns * 8);
                racc[0][0] += bv.x * ex2(acc[0][ns][0]) + bv.y * ex2(acc[0][ns][1]);
                racc[0][1] += bv.x * ex2(acc[0][ns][2]) + bv.y * ex2(acc[0][ns][3]);
                racc[1][0] += bv.x * ex2(acc[1][ns][0]) + bv.y * ex2(acc[1][ns][1]);
                racc[1][1] += bv.x * ex2(acc[1][ns][2]) + bv.y * ex2(acc[1][ns][3]);
            }
        }
        __syncthreads();   // compute done before buffer b is overwritten
    }

    // Reduce across the 4 lanes sharing each output row.
#pragma unroll
    for (int qs = 0; qs < 2; qs++)
#pragma unroll
        for (int h = 0; h < 2; h++) {
            float v = racc[qs][h];
            v += __shfl_xor_sync(0xffffffff, v, 1);
            v += __shfl_xor_sync(0xffffffff, v, 2);
            racc[qs][h] = v;
        }
    float* red = (float*)(smem + OFF_RED);
    if ((lane & 3) == 0) {
        int r = lane >> 2;
#pragma unroll
        for (int qs = 0; qs < 2; qs++)
#pragma unroll
            for (int h = 0; h < 2; h++)
                red[wn * 128 + wq * 32 + qs * 16 + h * 8 + r] = racc[qs][h];
    }
    __syncthreads();
    if (tid < 128) {
        int q = q0 + tid;
        if (q < Q) {
            float s = red[tid] + red[128 + tid];
            atomicAdd(&out[q], s * g_a[q] * (__ldg(norm) / (float)N));
        }
    }
}

// ---------------------------------------------------------------------------
extern "C" void kernel_launch(void* const* d_in, const int* in_sizes, int n_in,
                              void* d_out, int out_size) {
    const float* features = (const float*)d_in[0];
    const float* bw       = (const float*)d_in[1];
    const float* dataset  = (const float*)d_in[2];
    const float* norm     = (const float*)d_in[3];

    int Q = in_sizes[0] / DCONST;
    int N = in_sizes[2] / DCONST;
    int NT = (N + NTILE - 1) / NTILE;
    float* out = (float*)d_out;

    cudaFuncSetAttribute(kde_mma_kernel,
                         cudaFuncAttributeMaxDynamicSharedMemorySize, SMEM_TOTAL);

    int FB = (Q + 255) / 256;
    int XB = (NCAP + 255) / 256;
    prep_kernel<<<FB + XB, 256>>>(features, bw, dataset, out, Q, N, FB);

    dim3 grid((Q + QTILE - 1) / QTILE, NCHUNK);
    kde_mma_kernel<<<grid, 256, SMEM_TOTAL>>>(norm, out, Q, N, NT);
}

// round 16
// speedup vs baseline: 1.0466x; 1.0466x over previous
#include <cuda_runtime.h>
#include <cuda_fp16.h>
#include <cstdint>

// GaussianKDE via legacy mma.sync fp16 m16n8k16 (fp32 accum) + fused exp epilogue.
// R14 base (135.6us) with B fragments loaded via ldmatrix.m8n8.x4.b16:
// 16 ldmatrix per warp-tile instead of 64 LDS.32, shrinking the non-HMMA
// issue stream that serializes behind dispatch-blocking HMMAs.
// out[q] = (norm/N) * a[q] * sum_n b[n] * exp2((log2e*f_q) . x_n)

#define DCONST 64
#define QCAP   4096
#define NCAP   50048        // 391 * 128
#define QTILE  128
#define NTILE  128
#define NCHUNK 9            // 32 q-tiles * 9 = 288 blocks ~= 2 waves * 148 SMs
#define XS2    36           // uint32 (fp16x2) row stride: 32 pairs + 4 pad
#define LOG2E  1.44269504088896340736f

#define OFF_F  0
#define TILE_B (128 * XS2 * 4)          // 18432 bytes per 128-row fp16 tile
#define OFF_X  (OFF_F + TILE_B)         // 2 buffers
#define OFF_BS (OFF_X + 2 * TILE_B)     // bs[2][128] floats
#define OFF_RED (OFF_BS + 1024)         // red[256] floats
#define SMEM_TOTAL (OFF_RED + 1024)     // ~57 KB

__device__ uint32_t g_fh[QCAP * 32];    // fp16x2(log2e * f)
__device__ float    g_a[QCAP];
__device__ uint32_t g_xh[NCAP * 32];    // fp16x2(x)
__device__ float    g_b[NCAP];

// ---------------------------------------------------------------------------
__device__ __forceinline__ uint32_t smem_u32(const void* p) {
    uint32_t a;
    asm("{ .reg .u64 t; cvta.to.shared.u64 t, %1; cvt.u32.u64 %0, t; }"
        : "=r"(a) : "l"(p));
    return a;
}
__device__ __forceinline__ void cp16(uint32_t dst, const void* src) {
    asm volatile("cp.async.cg.shared.global [%0], [%1], 16;"
                 :: "r"(dst), "l"(src) : "memory");
}
__device__ __forceinline__ void mma16(float* d, const uint32_t* a,
                                      uint32_t b0, uint32_t b1) {
    asm volatile("mma.sync.aligned.m16n8k16.row.col.f32.f16.f16.f32 "
                 "{%0,%1,%2,%3}, {%4,%5,%6,%7}, {%8,%9}, {%0,%1,%2,%3};"
                 : "+f"(d[0]), "+f"(d[1]), "+f"(d[2]), "+f"(d[3])
                 : "r"(a[0]), "r"(a[1]), "r"(a[2]), "r"(a[3]),
                   "r"(b0), "r"(b1));
}
__device__ __forceinline__ void ldmx4(uint32_t& r0, uint32_t& r1,
                                      uint32_t& r2, uint32_t& r3, uint32_t addr) {
    asm volatile("ldmatrix.sync.aligned.m8n8.x4.shared.b16 {%0,%1,%2,%3}, [%4];"
                 : "=r"(r0), "=r"(r1), "=r"(r2), "=r"(r3) : "r"(addr));
}
__device__ __forceinline__ uint32_t pack_h2(float lo, float hi) {
    __half2 h = __floats2half2_rn(lo, hi);
    return *(uint32_t*)&h;
}
__device__ __forceinline__ float ex2(float x) {
    float r;
    asm("ex2.approx.f32 %0, %1;" : "=f"(r) : "f"(x));
    return r;
}

// ---------------------------------------------------------------------------
// Fused prep: blocks [0, FB) do the F side, blocks [FB, ...) the X side.
__global__ void prep_kernel(const float* __restrict__ feat,
                            const float* __restrict__ bw,
                            const float* __restrict__ ds,
                            float* __restrict__ out, int Q, int N, int FB) {
    int tid = threadIdx.x;
    if ((int)blockIdx.x < FB) {
        __shared__ float bws[DCONST][DCONST];
        for (int i = tid; i < DCONST * DCONST; i += 256)
            bws[i / DCONST][i % DCONST] = bw[i];
        __syncthreads();
        int q = blockIdx.x * 256 + tid;
        if (q >= Q) return;

        float r[DCONST];
        const float4* fr = (const float4*)(feat + (size_t)q * DCONST);
#pragma unroll
        for (int v = 0; v < DCONST / 4; v++) {
            float4 t = fr[v];
            r[4 * v + 0] = t.x; r[4 * v + 1] = t.y;
            r[4 * v + 2] = t.z; r[4 * v + 3] = t.w;
        }
        float fv[DCONST];
        float f2 = 0.0f;
#pragma unroll 4
        for (int d = 0; d < DCONST; d++) {
            float acc = 0.0f;
#pragma unroll
            for (int k = 0; k < DCONST; k++) acc = fmaf(r[k], bws[k][d], acc);
            fv[d] = acc * LOG2E;
            f2 = fmaf(acc, acc, f2);
        }
#pragma unroll
        for (int p = 0; p < 32; p++)
            g_fh[(size_t)q * 32 + p] = pack_h2(fv[2 * p], fv[2 * p + 1]);
        g_a[q] = expf(-0.5f * f2);
        out[q] = 0.0f;
    } else {
        int n = (blockIdx.x - FB) * 256 + tid;
        if (n >= NCAP) return;
        if (n < N) {
            float x2 = 0.0f;
            const float4* r4 = (const float4*)(ds + (size_t)n * DCONST);
#pragma unroll
            for (int v = 0; v < DCONST / 4; v++) {
                float4 t = r4[v];
                g_xh[(size_t)n * 32 + 2 * v + 0] = pack_h2(t.x, t.y);
                g_xh[(size_t)n * 32 + 2 * v + 1] = pack_h2(t.z, t.w);
                x2 = fmaf(t.x, t.x, x2); x2 = fmaf(t.y, t.y, x2);
                x2 = fmaf(t.z, t.z, x2); x2 = fmaf(t.w, t.w, x2);
            }
            g_b[n] = expf(-0.5f * x2);
        } else {
            uint4 z = make_uint4(0, 0, 0, 0);
#pragma unroll
            for (int i = 0; i < 8; i++)
                *(uint4*)(g_xh + (size_t)n * 32 + 4 * i) = z;
            g_b[n] = 0.0f;
        }
    }
}

// ---------------------------------------------------------------------------
// Main kernel: 128(Q) x 128(N) tile per block, 256 threads (8 warps).
// Warp = 32(Q) x 64(N). K=64 as 4 m16n8k16 steps. B via ldmatrix.x4:
// per (kk, ns-pair) one x4 loads matrices (ns_e,k-lo),(ns_e,k-hi),
// (ns_o,k-lo),(ns_o,k-hi) -> regs b0/b1 for two ns values.
__global__ __launch_bounds__(256, 1) void kde_mma_kernel(
    const float* __restrict__ norm, float* __restrict__ out,
    int Q, int N, int NT) {
    extern __shared__ char smem[];
    const uint32_t sb = smem_u32(smem);
    const uint32_t* fhu = (const uint32_t*)(smem + OFF_F);
    const int tid = threadIdx.x, lane = tid & 31, wid = tid >> 5;
    const int wq = wid >> 1, wn = wid & 1;
    const int q0 = blockIdx.x * QTILE;
    const int t0 = (blockIdx.y * NT) / NCHUNK;
    const int t1 = ((blockIdx.y + 1) * NT) / NCHUNK;
    const int cnt = t1 - t0;

    // Stage F tile and first X tile via cp.async (one group).
#pragma unroll
    for (int i = 0; i < 4; i++) {
        int e = tid + (i << 8);
        int row = e >> 3, c = e & 7;
        cp16(sb + OFF_F + row * (XS2 * 4) + c * 16,
             g_fh + (size_t)(q0 + row) * 32 + c * 4);
    }
    {
        int n0 = t0 * NTILE;
#pragma unroll
        for (int i = 0; i < 4; i++) {
            int e = tid + (i << 8);
            int row = e >> 3, c = e & 7;
            cp16(sb + OFF_X + row * (XS2 * 4) + c * 16,
                 g_xh + (size_t)(n0 + row) * 32 + c * 4);
        }
        if (tid < 32) cp16(sb + OFF_BS + tid * 16, g_b + n0 + tid * 4);
    }
    asm volatile("cp.async.commit_group;");

    const int rA = wq * 32 + (lane >> 2);
    const int cA = lane & 3;

    // ldmatrix per-lane address term (uint32 units within an X tile):
    //   matrix m = lane>>3: ns_off = (m>>1)*8 rows, khalf = m&1 (4 uint32)
    //   row-in-matrix = lane&7
    const uint32_t lm_lane =
        (uint32_t)((((lane >> 4) << 3) + (lane & 7)) * XS2 + ((lane >> 3) & 1) * 4);

    uint32_t ah[2][4][4];     // A fragments, 4 k-steps, register-resident
    bool a_loaded = false;
    float racc[2][2] = {{0.f, 0.f}, {0.f, 0.f}};

    for (int j = 0; j < cnt; j++) {
        const int b = j & 1;
        if (j + 1 < cnt) {
            // Prefetch next X tile into the other buffer.
            int n0 = (t0 + j + 1) * NTILE;
            int bb2 = (j + 1) & 1;
#pragma unroll
            for (int i = 0; i < 4; i++) {
                int e = tid + (i << 8);
                int row = e >> 3, c = e & 7;
                cp16(sb + OFF_X + bb2 * TILE_B + row * (XS2 * 4) + c * 16,
                     g_xh + (size_t)(n0 + row) * 32 + c * 4);
            }
            if (tid < 32) cp16(sb + OFF_BS + bb2 * 512 + tid * 16, g_b + n0 + tid * 4);
            asm volatile("cp.async.commit_group;");
            asm volatile("cp.async.wait_group 1;");
        } else {
            asm volatile("cp.async.wait_group 0;");
        }
        __syncthreads();

        if (!a_loaded) {    // F tile resident after first wait
            a_loaded = true;
#pragma unroll
            for (int qs = 0; qs < 2; qs++)
#pragma unroll
                for (int kk = 0; kk < 4; kk++) {
                    const uint32_t* p = fhu + (rA + qs * 16) * XS2 + kk * 8 + cA;
                    ah[qs][kk][0] = p[0];
                    ah[qs][kk][1] = p[8 * XS2];
                    ah[qs][kk][2] = p[4];
                    ah[qs][kk][3] = p[8 * XS2 + 4];
                }
        }

        // Base ldmatrix address for this buffer (byte address).
        const uint32_t xaddr = sb + OFF_X + (uint32_t)b * TILE_B +
                               ((uint32_t)(wn * 64) * XS2 + lm_lane) * 4;

        float acc[2][8][4];
#pragma unroll
        for (int qs = 0; qs < 2; qs++)
#pragma unroll
            for (int ns = 0; ns < 8; ns++)
#pragma unroll
                for (int i = 0; i < 4; i++) acc[qs][ns][i] = 0.f;

#pragma unroll
        for (int kk = 0; kk < 4; kk++) {
            uint32_t bb[8][2];
#pragma unroll
            for (int np = 0; np < 4; np++) {   // ns pair (2np, 2np+1)
                uint32_t addr = xaddr + (uint32_t)((np * 16 * XS2 + kk * 8) * 4);
                ldmx4(bb[2 * np][0], bb[2 * np][1],
                      bb[2 * np + 1][0], bb[2 * np + 1][1], addr);
            }
#pragma unroll
            for (int ns = 0; ns < 8; ns++) {
                mma16(acc[0][ns], ah[0][kk], bb[ns][0], bb[ns][1]);
                mma16(acc[1][ns], ah[1][kk], bb[ns][0], bb[ns][1]);
            }
        }

        // Fused epilogue: racc += b[n] * exp2(s). Padded rows: s=0, b=0 -> no-op.
        const float* bsp = (const float*)(smem + OFF_BS + b * 512)
                           + wn * 64 + 2 * (lane & 3);
#pragma unroll
        for (int ns = 0; ns < 8; ns++) {
            float2 bv = *(const float2*)(bsp + ns * 8);
            racc[0][0] = fmaf(bv.x, ex2(acc[0][ns][0]), racc[0][0]);
            racc[0][0] = fmaf(bv.y, ex2(acc[0][ns][1]), racc[0][0]);
            racc[0][1] = fmaf(bv.x, ex2(acc[0][ns][2]), racc[0][1]);
            racc[0][1] = fmaf(bv.y, ex2(acc[0][ns][3]), racc[0][1]);
            racc[1][0] = fmaf(bv.x, ex2(acc[1][ns][0]), racc[1][0]);
            racc[1][0] = fmaf(bv.y, ex2(acc[1][ns][1]), racc[1][0]);
            racc[1][1] = fmaf(bv.x, ex2(acc[1][ns][2]), racc[1][1]);
            racc[1][1] = fmaf(bv.y, ex2(acc[1][ns][3]), racc[1][1]);
        }
        __syncthreads();   // compute done before buffer b is overwritten
    }

    // Reduce across the 4 lanes sharing each output row.
#pragma unroll
    for (int qs = 0; qs < 2; qs++)
#pragma unroll
        for (int h = 0; h < 2; h++) {
            float v = racc[qs][h];
            v += __shfl_xor_sync(0xffffffff, v, 1);
            v += __shfl_xor_sync(0xffffffff, v, 2);
            racc[qs][h] = v;
        }
    float* red = (float*)(smem + OFF_RED);
    if ((lane & 3) == 0) {
        int r = lane >> 2;
#pragma unroll
        for (int qs = 0; qs < 2; qs++)
#pragma unroll
            for (int h = 0; h < 2; h++)
                red[wn * 128 + wq * 32 + qs * 16 + h * 8 + r] = racc[qs][h];
    }
    __syncthreads();
    if (tid < 128) {
        int q = q0 + tid;
        if (q < Q) {
            float s = red[tid] + red[128 + tid];
            atomicAdd(&out[q], s * g_a[q] * (__ldg(norm) / (float)N));
        }
    }
}

// ---------------------------------------------------------------------------
extern "C" void kernel_launch(void* const* d_in, const int* in_sizes, int n_in,
                              void* d_out, int out_size) {
    const float* features = (const float*)d_in[0];
    const float* bw       = (const float*)d_in[1];
    const float* dataset  = (const float*)d_in[2];
    const float* norm     = (const float*)d_in[3];

    int Q = in_sizes[0] / DCONST;
    int N = in_sizes[2] / DCONST;
    int NT = (N + NTILE - 1) / NTILE;
    float* out = (float*)d_out;

    cudaFuncSetAttribute(kde_mma_kernel,
                         cudaFuncAttributeMaxDynamicSharedMemorySize, SMEM_TOTAL);

    int FB = (Q + 255) / 256;
    int XB = (NCAP + 255) / 256;
    prep_kernel<<<FB + XB, 256>>>(features, bw, dataset, out, Q, N, FB);

    dim3 grid((Q + QTILE - 1) / QTILE, NCHUNK);
    kde_mma_kernel<<<grid, 256, SMEM_TOTAL>>>(norm, out, Q, N, NT);
}